// round 6
// baseline (speedup 1.0000x reference)
#include <cuda_runtime.h>
#include <cuda_bf16.h>

// RX(theta) on target bit TB over first N amplitudes: [[c, -is],[-is, c]].
template <int N, int TB>
__device__ __forceinline__ void rx_g(float (&sr)[32], float (&si)[32],
                                     float c, float s) {
#pragma unroll
    for (int i = 0; i < N; i++) {
        if (i & TB) continue;
        const int j = i | TB;
        float a0r = sr[i], a0i = si[i], a1r = sr[j], a1i = si[j];
        sr[i] = fmaf(c, a0r, s * a1i);
        si[i] = fmaf(c, a0i, -s * a1r);
        sr[j] = fmaf(c, a1r, s * a0i);
        si[j] = fmaf(c, a1i, -s * a0r);
    }
}

// Controlled X_theta: ctrl bit CB=1 -> [[0,-ie],[-i conj(e),0]] on TB,
// e = (er, ei) = e^{i theta/2}.
template <int N, int CB, int TB>
__device__ __forceinline__ void cu_g(float (&sr)[32], float (&si)[32],
                                     float er, float ei) {
#pragma unroll
    for (int i = 0; i < N; i++) {
        if (!(i & CB) || (i & TB)) continue;
        const int j = i | TB;
        float t0r = sr[i], t0i = si[i], t1r = sr[j], t1i = si[j];
        // t0' = (-i e) * t1 = (ei, -er) * t1
        sr[i] = fmaf(ei, t1r, er * t1i);
        si[i] = fmaf(ei, t1i, -er * t1r);
        // t1' = (-i conj(e)) * t0 = (-ei, -er) * t0
        sr[j] = fmaf(er, t0i, -ei * t0r);
        si[j] = -fmaf(ei, t0i, er * t0r);
    }
}

// One thread per patch, full 32-amp state in registers.
// (128,6): 85-reg cap (R1's natural allocation was 80) -> 6 blocks/SM,
// 24 resident warps, no forced spills.
#define TPB 128

__global__ void __launch_bounds__(TPB, 6)
sim_k(const float* __restrict__ x, const float* __restrict__ thetas,
      const float* __restrict__ phis, float* __restrict__ out) {
    __shared__ float2 sh_e[12];  // e^{i theta/2}
    __shared__ float2 sh_p[3];   // e^{i phi}

    int tid = threadIdx.x;
    if (tid < 12) {
        float s, c;
        __sincosf(0.5f * thetas[tid], &s, &c);
        sh_e[tid] = make_float2(c, s);
    } else if (tid < 15) {
        float s, c;
        __sincosf(phis[tid - 12], &s, &c);
        sh_p[tid - 12] = make_float2(c, s);
    }
    __syncthreads();

    int p = blockIdx.x * TPB + tid;
    int b = p >> 14;
    int rem = p & 16383;
    int h2 = rem >> 7;
    int w2 = rem & 127;
    const float* xb = x + (size_t)b * 196608 + (size_t)h2 * 512 + (size_t)w2 * 2;

    // All 6 pixel loads batched up front (MLP=6), sincos up front.
    // pix index = ch*4 + dy*2 + dx.
    float pcv[12], psv[12];
#pragma unroll
    for (int ch = 0; ch < 3; ch++) {
        float2 v0 = *reinterpret_cast<const float2*>(xb + ch * 65536);
        float2 v1 = *reinterpret_cast<const float2*>(xb + ch * 65536 + 256);
        int k = ch * 4;
        __sincosf(0.5f * v0.x, &psv[k + 0], &pcv[k + 0]);
        __sincosf(0.5f * v0.y, &psv[k + 1], &pcv[k + 1]);
        __sincosf(0.5f * v1.x, &psv[k + 2], &pcv[k + 2]);
        __sincosf(0.5f * v1.y, &psv[k + 3], &pcv[k + 3]);
    }

    // State index = a<<4 | b<<3 | c<<2 | d<<1 | e (wires 0..4).
    // Wire0 untouched until the first CPhase -> layer 0 on the 16-dim
    // subspace; both H branches identical until the fork. H's,
    // normalizations and Z-measure fold into ev = sum Re(psi_lo psi_hi^*).
    float sr[32], si[32];

    // Layer-0 RX block == product state: amp(k) = prod q * (-i)^popcount(k).
    {
        float ab[4], de[4];
        ab[0] = pcv[0] * pcv[1]; ab[1] = pcv[0] * psv[1];
        ab[2] = psv[0] * pcv[1]; ab[3] = psv[0] * psv[1];
        de[0] = pcv[2] * pcv[3]; de[1] = pcv[2] * psv[3];
        de[2] = psv[2] * pcv[3]; de[3] = psv[2] * psv[3];
#pragma unroll
        for (int k = 0; k < 16; k++) {
            float m = ab[k >> 2] * de[k & 3];
            int pc = __popc(k) & 3;  // compile-time folded
            sr[k] = (pc == 0) ? m : (pc == 2) ? -m : 0.0f;
            si[k] = (pc == 1) ? -m : (pc == 3) ? m : 0.0f;
        }
    }

    // Layer-0 CU gates on the 16-dim subspace.
    float2 e;
    e = sh_e[0]; cu_g<16, 8, 4>(sr, si, e.x, e.y);
    e = sh_e[1]; cu_g<16, 4, 2>(sr, si, e.x, e.y);
    e = sh_e[2]; cu_g<16, 2, 1>(sr, si, e.x, e.y);
    e = sh_e[3]; cu_g<16, 1, 8>(sr, si, e.x, e.y);

    // Fork: a=1 branch gets CPhase(phi_0) on its b=1 amplitudes.
    {
        float2 ph = sh_p[0];
#pragma unroll
        for (int j = 0; j < 16; j++) {
            if (j & 8) {
                sr[16 + j] = fmaf(ph.x, sr[j], -ph.y * si[j]);
                si[16 + j] = fmaf(ph.x, si[j], ph.y * sr[j]);
            } else {
                sr[16 + j] = sr[j];
                si[16 + j] = si[j];
            }
        }
    }

    // Layers 1, 2 on the full 32-dim state.
#pragma unroll
    for (int L = 1; L < 3; L++) {
        rx_g<32, 8>(sr, si, pcv[4 * L + 0], psv[4 * L + 0]);
        rx_g<32, 4>(sr, si, pcv[4 * L + 1], psv[4 * L + 1]);
        rx_g<32, 2>(sr, si, pcv[4 * L + 2], psv[4 * L + 2]);
        rx_g<32, 1>(sr, si, pcv[4 * L + 3], psv[4 * L + 3]);
        e = sh_e[4 * L + 0]; cu_g<32, 8, 4>(sr, si, e.x, e.y);
        e = sh_e[4 * L + 1]; cu_g<32, 4, 2>(sr, si, e.x, e.y);
        e = sh_e[4 * L + 2]; cu_g<32, 2, 1>(sr, si, e.x, e.y);
        e = sh_e[4 * L + 3]; cu_g<32, 1, 8>(sr, si, e.x, e.y);
        // CPhase(phi_L) on wires 0,1: bit4 & bit3 set -> indices 24..31.
        float2 ph = sh_p[L];
#pragma unroll
        for (int j = 24; j < 32; j++) {
            float r = sr[j], m = si[j];
            sr[j] = fmaf(ph.x, r, -ph.y * m);
            si[j] = fmaf(ph.x, m, ph.y * r);
        }
    }

    // <Z_0> = sum_k Re(psi_lo[k] * conj(psi_hi[k])).
    float ev = 0.f;
#pragma unroll
    for (int j = 0; j < 16; j++) {
        ev = fmaf(sr[j], sr[j + 16], ev);
        ev = fmaf(si[j], si[j + 16], ev);
    }
    out[p] = ev;
}

extern "C" void kernel_launch(void* const* d_in, const int* in_sizes, int n_in,
                              void* d_out, int out_size) {
    const float* x = nullptr;
    const float* thetas = nullptr;
    const float* phis = nullptr;
    for (int i = 0; i < n_in; i++) {
        if (in_sizes[i] == 12) thetas = (const float*)d_in[i];
        else if (in_sizes[i] == 3) phis = (const float*)d_in[i];
        else x = (const float*)d_in[i];
    }
    float* out = (float*)d_out;

    int grid = (out_size + TPB - 1) / TPB;  // 2048 for P = 262144
    sim_k<<<grid, TPB>>>(x, thetas, phis, out);
}

// round 7
// speedup vs baseline: 1.2183x; 1.2183x over previous
#include <cuda_runtime.h>
#include <cuda_bf16.h>

// Unnormalized RX: (I - i*tau*X), tau = tan(theta/2). The cos(theta/2)
// normalization factors into a global scalar S applied once at the end
// (ev = S^2 * ev~). 4 FMA per butterfly pair (negations fold into FFMA).
template <int N, int TB>
__device__ __forceinline__ void rx_t(float (&sr)[32], float (&si)[32],
                                     float tau) {
#pragma unroll
    for (int i = 0; i < N; i++) {
        if (i & TB) continue;
        const int j = i | TB;
        float t0r = sr[i], t0i = si[i], t1r = sr[j], t1i = si[j];
        sr[i] = fmaf(tau, t1i, t0r);
        si[i] = fmaf(-tau, t1r, t0i);
        sr[j] = fmaf(tau, t0i, t1r);
        si[j] = fmaf(-tau, t0r, t1i);
    }
}

// Controlled X_theta: ctrl bit CB=1 -> [[0,-ie],[-i conj(e),0]] on TB,
// e = (er, ei) = e^{i theta/2}. Anti-diagonal: 8 FMA per pair (minimal).
template <int N, int CB, int TB>
__device__ __forceinline__ void cu_g(float (&sr)[32], float (&si)[32],
                                     float er, float ei) {
#pragma unroll
    for (int i = 0; i < N; i++) {
        if (!(i & CB) || (i & TB)) continue;
        const int j = i | TB;
        float t0r = sr[i], t0i = si[i], t1r = sr[j], t1i = si[j];
        // t0' = (-i e) * t1 = (ei, -er) * t1
        sr[i] = fmaf(ei, t1r, er * t1i);
        si[i] = fmaf(ei, t1i, -er * t1r);
        // t1' = (-i conj(e)) * t0 = (-ei, -er) * t0
        sr[j] = fmaf(er, t0i, -ei * t0r);
        si[j] = -fmaf(ei, t0i, er * t0r);
    }
}

#define TPB 128

__global__ void __launch_bounds__(TPB, 6)
sim_k(const float* __restrict__ x, const float* __restrict__ thetas,
      const float* __restrict__ phis, float* __restrict__ out) {
    __shared__ float2 sh_e[12];  // e^{i theta/2}
    __shared__ float2 sh_p[3];   // e^{i phi}

    int tid = threadIdx.x;
    if (tid < 12) {
        float s, c;
        __sincosf(0.5f * thetas[tid], &s, &c);
        sh_e[tid] = make_float2(c, s);
    } else if (tid < 15) {
        float s, c;
        __sincosf(phis[tid - 12], &s, &c);
        sh_p[tid - 12] = make_float2(c, s);
    }
    __syncthreads();

    int p = blockIdx.x * TPB + tid;
    int b = p >> 14;
    int rem = p & 16383;
    int h2 = rem >> 7;
    int w2 = rem & 127;
    const float* xb = x + (size_t)b * 196608 + (size_t)h2 * 512 + (size_t)w2 * 2;

    // All 6 pixel loads batched up front (MLP=6). Per-angle tau = tan(x/2)
    // and running scale S = prod cos(x/2). pix index = ch*4 + dy*2 + dx.
    float tv[12];
    float S = 1.0f;
#pragma unroll
    for (int ch = 0; ch < 3; ch++) {
        float2 v0 = *reinterpret_cast<const float2*>(xb + ch * 65536);
        float2 v1 = *reinterpret_cast<const float2*>(xb + ch * 65536 + 256);
        float a[4] = {v0.x, v0.y, v1.x, v1.y};
#pragma unroll
        for (int q = 0; q < 4; q++) {
            float s, c;
            __sincosf(0.5f * a[q], &s, &c);
            tv[ch * 4 + q] = __fdividef(s, c);
            S *= c;
        }
    }

    // State index = a<<4 | b<<3 | c<<2 | d<<1 | e (wires 0..4).
    // Wire0 untouched until the first CPhase -> layer 0 on the 16-dim
    // subspace; both H branches identical until the fork. H's,
    // normalizations, RX cosines and Z-measure fold into ev = S^2 * ev~.
    float sr[32], si[32];

    // Layer-0 RX block == product state (unnormalized):
    // amp(k) = prod_{bit set} tau_w * (-i)^popcount(k).
    {
        float ab[4], de[4];
        ab[0] = 1.0f;  ab[1] = tv[1];
        ab[2] = tv[0]; ab[3] = tv[0] * tv[1];
        de[0] = 1.0f;  de[1] = tv[3];
        de[2] = tv[2]; de[3] = tv[2] * tv[3];
#pragma unroll
        for (int k = 0; k < 16; k++) {
            float m = ab[k >> 2] * de[k & 3];
            int pc = __popc(k) & 3;  // compile-time folded
            sr[k] = (pc == 0) ? m : (pc == 2) ? -m : 0.0f;
            si[k] = (pc == 1) ? -m : (pc == 3) ? m : 0.0f;
        }
    }

    // Layer-0 CU gates on the 16-dim subspace.
    float2 e;
    e = sh_e[0]; cu_g<16, 8, 4>(sr, si, e.x, e.y);
    e = sh_e[1]; cu_g<16, 4, 2>(sr, si, e.x, e.y);
    e = sh_e[2]; cu_g<16, 2, 1>(sr, si, e.x, e.y);
    e = sh_e[3]; cu_g<16, 1, 8>(sr, si, e.x, e.y);

    // Fork: a=1 branch gets CPhase(phi_0) on its b=1 amplitudes.
    {
        float2 ph = sh_p[0];
#pragma unroll
        for (int j = 0; j < 16; j++) {
            if (j & 8) {
                sr[16 + j] = fmaf(ph.x, sr[j], -ph.y * si[j]);
                si[16 + j] = fmaf(ph.x, si[j], ph.y * sr[j]);
            } else {
                sr[16 + j] = sr[j];
                si[16 + j] = si[j];
            }
        }
    }

    // ---- Layer 1 (with CPhase) ----
    rx_t<32, 8>(sr, si, tv[4]);
    rx_t<32, 4>(sr, si, tv[5]);
    rx_t<32, 2>(sr, si, tv[6]);
    rx_t<32, 1>(sr, si, tv[7]);
    e = sh_e[4]; cu_g<32, 8, 4>(sr, si, e.x, e.y);
    e = sh_e[5]; cu_g<32, 4, 2>(sr, si, e.x, e.y);
    e = sh_e[6]; cu_g<32, 2, 1>(sr, si, e.x, e.y);
    e = sh_e[7]; cu_g<32, 1, 8>(sr, si, e.x, e.y);
    {
        float2 ph = sh_p[1];
#pragma unroll
        for (int j = 24; j < 32; j++) {
            float r = sr[j], m = si[j];
            sr[j] = fmaf(ph.x, r, -ph.y * m);
            si[j] = fmaf(ph.x, m, ph.y * r);
        }
    }

    // ---- Layer 2 (CPhase folded into the final sum) ----
    rx_t<32, 8>(sr, si, tv[8]);
    rx_t<32, 4>(sr, si, tv[9]);
    rx_t<32, 2>(sr, si, tv[10]);
    rx_t<32, 1>(sr, si, tv[11]);
    e = sh_e[8];  cu_g<32, 8, 4>(sr, si, e.x, e.y);
    e = sh_e[9];  cu_g<32, 4, 2>(sr, si, e.x, e.y);
    e = sh_e[10]; cu_g<32, 2, 1>(sr, si, e.x, e.y);
    e = sh_e[11]; cu_g<32, 1, 8>(sr, si, e.x, e.y);

    // <Z_0> = sum_k Re(psi_lo[k] * conj(psi_hi[k])), with the layer-2
    // CPhase e^{i phi2} on hi-branch b=1 amps folded in:
    // ev~ = A + cos(phi2)*Br + sin(phi2)*Bi, then ev = S^2 * ev~.
    float A = 0.f, Br = 0.f, Bi = 0.f;
#pragma unroll
    for (int j = 0; j < 8; j++) {
        A = fmaf(sr[j], sr[j + 16], A);
        A = fmaf(si[j], si[j + 16], A);
    }
#pragma unroll
    for (int j = 8; j < 16; j++) {
        Br = fmaf(sr[j], sr[j + 16], Br);
        Br = fmaf(si[j], si[j + 16], Br);
        Bi = fmaf(si[j], sr[j + 16], Bi);
        Bi = fmaf(-sr[j], si[j + 16], Bi);
    }
    float2 ph2 = sh_p[2];
    float ev = A + fmaf(ph2.x, Br, ph2.y * Bi);
    out[p] = ev * S * S;
}

extern "C" void kernel_launch(void* const* d_in, const int* in_sizes, int n_in,
                              void* d_out, int out_size) {
    const float* x = nullptr;
    const float* thetas = nullptr;
    const float* phis = nullptr;
    for (int i = 0; i < n_in; i++) {
        if (in_sizes[i] == 12) thetas = (const float*)d_in[i];
        else if (in_sizes[i] == 3) phis = (const float*)d_in[i];
        else x = (const float*)d_in[i];
    }
    float* out = (float*)d_out;

    int grid = (out_size + TPB - 1) / TPB;  // 2048 for P = 262144
    sim_k<<<grid, TPB>>>(x, thetas, phis, out);
}

// round 8
// speedup vs baseline: 1.3662x; 1.1214x over previous
#include <cuda_runtime.h>
#include <cuda_bf16.h>

// ---- constexpr permutation of the per-layer CU block ----
// Each CU gate is a generalized permutation (swap-with-phase). The index part
// of one layer's CU(1,2)CU(2,3)CU(3,4)CU(4,1) is this fixed permutation:
__host__ __device__ constexpr int sig1(int k) {
    int b = (k >> 3) & 1, c = (k >> 2) & 1, d = (k >> 1) & 1, e = k & 1;
    if (b) c ^= 1;
    if (c) d ^= 1;
    if (d) e ^= 1;
    if (e) b ^= 1;
    return b * 8 + c * 4 + d * 2 + e;
}
__host__ __device__ constexpr int sigp(int k, int n) {
    for (int i = 0; i < n; i++) k = sig1(k);
    return k;
}
__host__ __device__ constexpr int isigp(int j, int n) {
    for (int k = 0; k < 16; k++)
        if (sigp(k, n) == j) return k;
    return 0;
}

// Runtime phase walk for basis state k through one layer's 4 CU gates.
// Phase factor when target bit goes 1->0 is -i*e = (s, -c); 0->1 is
// -i*conj(e) = (-s, -c), with e = e^{i theta/2} = (c, s).
__device__ __forceinline__ void cu_walk(int k, const float* th,
                                        float& pr, float& pi) {
    pr = 1.f; pi = 0.f;
    int b = (k >> 3) & 1, c = (k >> 2) & 1, d = (k >> 1) & 1, e = k & 1;
    float s, cc, fr, fi, nr, ni;
#define CUW(CTRL, TGT, IDX)                                   \
    if (CTRL) {                                               \
        __sincosf(0.5f * th[IDX], &s, &cc);                   \
        fr = (TGT) ? s : -s; fi = -cc;                        \
        nr = pr * fr - pi * fi; ni = pr * fi + pi * fr;       \
        pr = nr; pi = ni; TGT ^= 1;                           \
    }
    CUW(b, c, 0) CUW(c, d, 1) CUW(d, e, 2) CUW(e, b, 3)
#undef CUW
}

// Unnormalized RX (I - i*tau*X) on wire TB, state stored under perm sig^N:
// slot k holds logical index sigp(k,N). 4 FMA per butterfly pair.
template <int TB, int N>
__device__ __forceinline__ void rx_t(float (&sr)[32], float (&si)[32],
                                     float tau) {
#pragma unroll
    for (int p = 0; p < 16; p++) {
        const int lp = sigp(p, N);
        if (lp & TB) continue;
        const int q = isigp(lp | TB, N);
        {
            float t0r = sr[p], t0i = si[p], t1r = sr[q], t1i = si[q];
            sr[p] = fmaf(tau, t1i, t0r); si[p] = fmaf(-tau, t1r, t0i);
            sr[q] = fmaf(tau, t0i, t1r); si[q] = fmaf(-tau, t0r, t1i);
        }
        {
            float t0r = sr[p + 16], t0i = si[p + 16];
            float t1r = sr[q + 16], t1i = si[q + 16];
            sr[p + 16] = fmaf(tau, t1i, t0r); si[p + 16] = fmaf(-tau, t1r, t0i);
            sr[q + 16] = fmaf(tau, t0i, t1r); si[q + 16] = fmaf(-tau, t0r, t1i);
        }
    }
}

// Whole CU block of a layer = in-place per-slot phase multiply (the index
// permutation is absorbed into compile-time relabeling). Perm at input = sig^N.
template <int N>
__device__ __forceinline__ void cu_tab(float (&sr)[32], float (&si)[32],
                                       const float2* tlo, const float2* thi) {
#pragma unroll
    for (int k = 0; k < 16; k++) {
        const int l = sigp(k, N);
        float2 pl = tlo[l];
        float r = sr[k], m = si[k];
        sr[k] = fmaf(pl.x, r, -pl.y * m);
        si[k] = fmaf(pl.x, m, pl.y * r);
        float2 ph = thi[l];
        float r2 = sr[k + 16], m2 = si[k + 16];
        sr[k + 16] = fmaf(ph.x, r2, -ph.y * m2);
        si[k + 16] = fmaf(ph.x, m2, ph.y * r2);
    }
}

#define TPB 128

__global__ void __launch_bounds__(TPB, 6)
sim_k(const float* __restrict__ x, const float* __restrict__ thetas,
      const float* __restrict__ phis, float* __restrict__ out) {
    // Phase tables (logical-indexed) shared by the whole block.
    __shared__ float2 sh_t0[16];    // layer-0 CU phase x (-i)^popc(k) init fold
    __shared__ float2 sh_t1lo[16];  // layer-1 CU phase
    __shared__ float2 sh_t1hi[16];  // layer-1 CU phase with CPhase(phi1) fold
    __shared__ float2 sh_t2[16];    // layer-2 CU phase
    __shared__ float2 sh_ph[2];     // e^{i phi0}, e^{i phi2}

    int tid = threadIdx.x;
    if (tid < 48) {
        int L = tid >> 4, k = tid & 15;
        float pr, pi;
        cu_walk(k, thetas + 4 * L, pr, pi);
        if (L == 0) {
            int pc = __popc(k) & 3;  // fold (-i)^popc(k) from the RX init
            float nr, ni;
            if (pc == 0)      { nr = pr;  ni = pi;  }
            else if (pc == 1) { nr = pi;  ni = -pr; }
            else if (pc == 2) { nr = -pr; ni = -pi; }
            else              { nr = -pi; ni = pr;  }
            sh_t0[k] = make_float2(nr, ni);
        } else if (L == 1) {
            sh_t1lo[k] = make_float2(pr, pi);
            float sp, cp;
            __sincosf(phis[1], &sp, &cp);
            if (sig1(k) & 8)  // CPhase acts on logical b-bit AFTER the perm
                sh_t1hi[k] = make_float2(pr * cp - pi * sp, pr * sp + pi * cp);
            else
                sh_t1hi[k] = make_float2(pr, pi);
        } else {
            sh_t2[k] = make_float2(pr, pi);
        }
    } else if (tid == 48) {
        float s, c; __sincosf(phis[0], &s, &c); sh_ph[0] = make_float2(c, s);
    } else if (tid == 49) {
        float s, c; __sincosf(phis[2], &s, &c); sh_ph[1] = make_float2(c, s);
    }
    __syncthreads();

    int p = blockIdx.x * TPB + tid;
    int b = p >> 14;
    int rem = p & 16383;
    int h2 = rem >> 7;
    int w2 = rem & 127;
    const float* xb = x + (size_t)b * 196608 + (size_t)h2 * 512 + (size_t)w2 * 2;

    // All 6 pixel loads batched (MLP=6); tau = tan(x/2), S = prod cos(x/2).
    float tv[12];
    float S = 1.0f;
#pragma unroll
    for (int ch = 0; ch < 3; ch++) {
        float2 v0 = *reinterpret_cast<const float2*>(xb + ch * 65536);
        float2 v1 = *reinterpret_cast<const float2*>(xb + ch * 65536 + 256);
        float a[4] = {v0.x, v0.y, v1.x, v1.y};
#pragma unroll
        for (int q = 0; q < 4; q++) {
            float s, c;
            __sincosf(0.5f * a[q], &s, &c);
            tv[ch * 4 + q] = __fdividef(s, c);
            S *= c;
        }
    }

    // State slots 0..15 = lo (wire0=0) branch, 16..31 = hi. Wire0 is only
    // touched by the (folded) H's and CPhases. ev = S^2 * Re<psi_lo|psi_hi>.
    float sr[32], si[32];

    // Init: product state x layer-0 CU phases in one pass (m is real):
    // slot k <- m(k) * sh_t0[k]; afterwards slot k holds logical sig1(k).
    {
        float abt[4] = {1.f, tv[1], tv[0], tv[0] * tv[1]};
        float det[4] = {1.f, tv[3], tv[2], tv[2] * tv[3]};
#pragma unroll
        for (int k = 0; k < 16; k++) {
            float m = abt[k >> 2] * det[k & 3];
            float2 t0 = sh_t0[k];
            sr[k] = m * t0.x;
            si[k] = m * t0.y;
        }
    }

    // Fork: hi branch gets CPhase(phi0) on logical b=1 amps (= sig1(k)&8).
    {
        float2 p0 = sh_ph[0];
#pragma unroll
        for (int k = 0; k < 16; k++) {
            if (sig1(k) & 8) {
                sr[k + 16] = fmaf(p0.x, sr[k], -p0.y * si[k]);
                si[k + 16] = fmaf(p0.x, si[k], p0.y * sr[k]);
            } else {
                sr[k + 16] = sr[k];
                si[k + 16] = si[k];
            }
        }
    }

    // Layer 1 (perm sig^1 in effect), CPhase(phi1) folded into hi table.
    rx_t<8, 1>(sr, si, tv[4]);
    rx_t<4, 1>(sr, si, tv[5]);
    rx_t<2, 1>(sr, si, tv[6]);
    rx_t<1, 1>(sr, si, tv[7]);
    cu_tab<1>(sr, si, sh_t1lo, sh_t1hi);

    // Layer 2 (perm sig^2), CPhase(phi2) folded into the final sum.
    rx_t<8, 2>(sr, si, tv[8]);
    rx_t<4, 2>(sr, si, tv[9]);
    rx_t<2, 2>(sr, si, tv[10]);
    rx_t<1, 2>(sr, si, tv[11]);
    cu_tab<2>(sr, si, sh_t2, sh_t2);

    // Final (perm sig^3): ev~ = A + cos(phi2)*Br + sin(phi2)*Bi.
    float A = 0.f, Br = 0.f, Bi = 0.f;
#pragma unroll
    for (int k = 0; k < 16; k++) {
        const int l = sigp(k, 3);
        float lr = sr[k], li = si[k], hr = sr[k + 16], hm = si[k + 16];
        if (l & 8) {
            Br = fmaf(lr, hr, Br);
            Br = fmaf(li, hm, Br);
            Bi = fmaf(li, hr, Bi);
            Bi = fmaf(-lr, hm, Bi);
        } else {
            A = fmaf(lr, hr, A);
            A = fmaf(li, hm, A);
        }
    }
    float2 p2 = sh_ph[1];
    float ev = A + fmaf(p2.x, Br, p2.y * Bi);
    out[p] = ev * S * S;
}

extern "C" void kernel_launch(void* const* d_in, const int* in_sizes, int n_in,
                              void* d_out, int out_size) {
    const float* x = nullptr;
    const float* thetas = nullptr;
    const float* phis = nullptr;
    for (int i = 0; i < n_in; i++) {
        if (in_sizes[i] == 12) thetas = (const float*)d_in[i];
        else if (in_sizes[i] == 3) phis = (const float*)d_in[i];
        else x = (const float*)d_in[i];
    }
    float* out = (float*)d_out;

    int grid = (out_size + TPB - 1) / TPB;  // 2048 for P = 262144
    sim_k<<<grid, TPB>>>(x, thetas, phis, out);
}

// round 9
// speedup vs baseline: 1.5517x; 1.1358x over previous
#include <cuda_runtime.h>
#include <cuda_bf16.h>

// ---- constexpr permutation of the per-layer CU block ----
__host__ __device__ constexpr int sig1(int k) {
    int b = (k >> 3) & 1, c = (k >> 2) & 1, d = (k >> 1) & 1, e = k & 1;
    if (b) c ^= 1;
    if (c) d ^= 1;
    if (d) e ^= 1;
    if (e) b ^= 1;
    return b * 8 + c * 4 + d * 2 + e;
}
__host__ __device__ constexpr int sigp(int k, int n) {
    for (int i = 0; i < n; i++) k = sig1(k);
    return k;
}
__host__ __device__ constexpr int isigp(int j, int n) {
    for (int k = 0; k < 16; k++)
        if (sigp(k, n) == j) return k;
    return 0;
}

// Runtime phase walk for basis state k through one layer's 4 CU gates.
// Target 1->0: -i*e = (s, -c); 0->1: -i*conj(e) = (-s, -c); e = e^{i th/2}.
__device__ __forceinline__ void cu_walk(int k, const float* th,
                                        float& pr, float& pi) {
    pr = 1.f; pi = 0.f;
    int b = (k >> 3) & 1, c = (k >> 2) & 1, d = (k >> 1) & 1, e = k & 1;
    float s, cc, fr, fi, nr, ni;
#define CUW(CTRL, TGT, IDX)                                   \
    if (CTRL) {                                               \
        __sincosf(0.5f * th[IDX], &s, &cc);                   \
        fr = (TGT) ? s : -s; fi = -cc;                        \
        nr = pr * fr - pi * fi; ni = pr * fi + pi * fr;       \
        pr = nr; pi = ni; TGT ^= 1;                           \
    }
    CUW(b, c, 0) CUW(c, d, 1) CUW(d, e, 2) CUW(e, b, 3)
#undef CUW
}

// Unnormalized RX (I - i*tau*X) on wire TB, both branches, perm sig^N.
template <int TB, int N>
__device__ __forceinline__ void rx_t(float (&sr)[32], float (&si)[32],
                                     float tau) {
#pragma unroll
    for (int p = 0; p < 16; p++) {
        const int lp = sigp(p, N);
        if (lp & TB) continue;
        const int q = isigp(lp | TB, N);
        {
            float t0r = sr[p], t0i = si[p], t1r = sr[q], t1i = si[q];
            sr[p] = fmaf(tau, t1i, t0r); si[p] = fmaf(-tau, t1r, t0i);
            sr[q] = fmaf(tau, t0i, t1r); si[q] = fmaf(-tau, t0r, t1i);
        }
        {
            float t0r = sr[p + 16], t0i = si[p + 16];
            float t1r = sr[q + 16], t1i = si[q + 16];
            sr[p + 16] = fmaf(tau, t1i, t0r); si[p + 16] = fmaf(-tau, t1r, t0i);
            sr[q + 16] = fmaf(tau, t0i, t1r); si[q + 16] = fmaf(-tau, t0r, t1i);
        }
    }
}

// Same, but on the lo 16 slots only (pre-fork shared state).
template <int TB, int N>
__device__ __forceinline__ void rx16_t(float (&sr)[32], float (&si)[32],
                                       float tau) {
#pragma unroll
    for (int p = 0; p < 16; p++) {
        const int lp = sigp(p, N);
        if (lp & TB) continue;
        const int q = isigp(lp | TB, N);
        float t0r = sr[p], t0i = si[p], t1r = sr[q], t1i = si[q];
        sr[p] = fmaf(tau, t1i, t0r); si[p] = fmaf(-tau, t1r, t0i);
        sr[q] = fmaf(tau, t0i, t1r); si[q] = fmaf(-tau, t0r, t1i);
    }
}

// Layer-1 CU block = per-slot phase multiply (perm handled by relabeling).
template <int N>
__device__ __forceinline__ void cu_tab(float (&sr)[32], float (&si)[32],
                                       const float2* tlo, const float2* thi) {
#pragma unroll
    for (int k = 0; k < 16; k++) {
        const int l = sigp(k, N);
        float2 pl = tlo[l];
        float r = sr[k], m = si[k];
        sr[k] = fmaf(pl.x, r, -pl.y * m);
        si[k] = fmaf(pl.x, m, pl.y * r);
        float2 ph = thi[l];
        float r2 = sr[k + 16], m2 = si[k + 16];
        sr[k + 16] = fmaf(ph.x, r2, -ph.y * m2);
        si[k + 16] = fmaf(ph.x, m2, ph.y * r2);
    }
}

#define TPB 128

__global__ void __launch_bounds__(TPB, 6)
sim_k(const float* __restrict__ x, const float* __restrict__ thetas,
      const float* __restrict__ phis, float* __restrict__ out) {
    // Logical-indexed phase tables, shared per block. NOTE: the layer-2 CU
    // phase table is GONE — identical unit phase on lo & hi cancels in
    // Re(psi_lo conj(psi_hi)); only its (compile-time) permutation survives.
    __shared__ float2 sh_t0[16];    // layer-0 CU phase x (-i)^popc init fold
    __shared__ float2 sh_t1lo[16];  // layer-1 CU phase
    __shared__ float2 sh_t1hi[16];  // layer-1 CU phase + CPhase(phi1) fold
    __shared__ float2 sh_ph[2];     // e^{i phi0}, e^{i phi2}

    int tid = threadIdx.x;
    if (tid < 32) {
        int L = tid >> 4, k = tid & 15;
        float pr, pi;
        cu_walk(k, thetas + 4 * L, pr, pi);
        if (L == 0) {
            int pc = __popc(k) & 3;  // fold (-i)^popc(k) from the RX init
            float nr, ni;
            if (pc == 0)      { nr = pr;  ni = pi;  }
            else if (pc == 1) { nr = pi;  ni = -pr; }
            else if (pc == 2) { nr = -pr; ni = -pi; }
            else              { nr = -pi; ni = pr;  }
            sh_t0[k] = make_float2(nr, ni);
        } else {
            sh_t1lo[k] = make_float2(pr, pi);
            float sp, cp;
            __sincosf(phis[1], &sp, &cp);
            if (sig1(k) & 8)  // CPhase acts on logical b-bit AFTER the perm
                sh_t1hi[k] = make_float2(pr * cp - pi * sp, pr * sp + pi * cp);
            else
                sh_t1hi[k] = make_float2(pr, pi);
        }
    } else if (tid == 32) {
        float s, c; __sincosf(phis[0], &s, &c); sh_ph[0] = make_float2(c, s);
    } else if (tid == 33) {
        float s, c; __sincosf(phis[2], &s, &c); sh_ph[1] = make_float2(c, s);
    }
    __syncthreads();

    int p = blockIdx.x * TPB + tid;
    int b = p >> 14;
    int rem = p & 16383;
    int h2 = rem >> 7;
    int w2 = rem & 127;
    const float* xb = x + (size_t)b * 196608 + (size_t)h2 * 512 + (size_t)w2 * 2;

    // All 6 pixel loads batched (MLP=6); tau = tan(x/2), S = prod cos(x/2).
    float tv[12];
    float S = 1.0f;
#pragma unroll
    for (int ch = 0; ch < 3; ch++) {
        float2 v0 = *reinterpret_cast<const float2*>(xb + ch * 65536);
        float2 v1 = *reinterpret_cast<const float2*>(xb + ch * 65536 + 256);
        float a[4] = {v0.x, v0.y, v1.x, v1.y};
#pragma unroll
        for (int q = 0; q < 4; q++) {
            float s, c;
            __sincosf(0.5f * a[q], &s, &c);
            tv[ch * 4 + q] = __fdividef(s, c);
            S *= c;
        }
    }

    // Slots 0..15 = lo (wire0=0) branch, 16..31 = hi. ev = S^2 Re<lo|hi*>.
    float sr[32], si[32];

    // Init: product state x layer-0 CU phases (m real); slot k holds sig1(k).
    {
        float abt[4] = {1.f, tv[1], tv[0], tv[0] * tv[1]};
        float det[4] = {1.f, tv[3], tv[2], tv[2] * tv[3]};
#pragma unroll
        for (int k = 0; k < 16; k++) {
            float m = abt[k >> 2] * det[k & 3];
            float2 t0 = sh_t0[k];
            sr[k] = m * t0.x;
            si[k] = m * t0.y;
        }
    }

    // Layer-1 RX on wires 2,3,4 (bits 4,2,1): these commute with the fork's
    // diagonal phase on logical bit 8, so run them ONCE on the shared state.
    rx16_t<4, 1>(sr, si, tv[5]);
    rx16_t<2, 1>(sr, si, tv[6]);
    rx16_t<1, 1>(sr, si, tv[7]);

    // Fork: hi branch = lo with CPhase(phi0) on logical b=1 amps (sig1(k)&8).
    {
        float2 p0 = sh_ph[0];
#pragma unroll
        for (int k = 0; k < 16; k++) {
            if (sig1(k) & 8) {
                sr[k + 16] = fmaf(p0.x, sr[k], -p0.y * si[k]);
                si[k + 16] = fmaf(p0.x, si[k], p0.y * sr[k]);
            } else {
                sr[k + 16] = sr[k];
                si[k + 16] = si[k];
            }
        }
    }

    // Remaining layer-1 RX on wire 1 (bit 8), both branches; then CU phases
    // (CPhase(phi1) folded into the hi table).
    rx_t<8, 1>(sr, si, tv[4]);
    cu_tab<1>(sr, si, sh_t1lo, sh_t1hi);

    // Layer 2 (perm sig^2): RX only — the CU phase multiply cancels in the
    // final bilinear, and CPhase(phi2) is folded into the sum below.
    rx_t<8, 2>(sr, si, tv[8]);
    rx_t<4, 2>(sr, si, tv[9]);
    rx_t<2, 2>(sr, si, tv[10]);
    rx_t<1, 2>(sr, si, tv[11]);

    // Final (virtual perm sig^3): ev~ = A + cos(phi2)*Br + sin(phi2)*Bi.
    float A = 0.f, Br = 0.f, Bi = 0.f;
#pragma unroll
    for (int k = 0; k < 16; k++) {
        const int l = sigp(k, 3);
        float lr = sr[k], li = si[k], hr = sr[k + 16], hm = si[k + 16];
        if (l & 8) {
            Br = fmaf(lr, hr, Br);
            Br = fmaf(li, hm, Br);
            Bi = fmaf(li, hr, Bi);
            Bi = fmaf(-lr, hm, Bi);
        } else {
            A = fmaf(lr, hr, A);
            A = fmaf(li, hm, A);
        }
    }
    float2 p2 = sh_ph[1];
    float ev = A + fmaf(p2.x, Br, p2.y * Bi);
    out[p] = ev * S * S;
}

extern "C" void kernel_launch(void* const* d_in, const int* in_sizes, int n_in,
                              void* d_out, int out_size) {
    const float* x = nullptr;
    const float* thetas = nullptr;
    const float* phis = nullptr;
    for (int i = 0; i < n_in; i++) {
        if (in_sizes[i] == 12) thetas = (const float*)d_in[i];
        else if (in_sizes[i] == 3) phis = (const float*)d_in[i];
        else x = (const float*)d_in[i];
    }
    float* out = (float*)d_out;

    int grid = (out_size + TPB - 1) / TPB;  // 2048 for P = 262144
    sim_k<<<grid, TPB>>>(x, thetas, phis, out);
}